// round 10
// baseline (speedup 1.0000x reference)
#include <cuda_runtime.h>

// Problem dims (fixed by the dataset)
#define BDIM 64
#define NDIM 512
#define HDIM 2048
#define KP     (NDIM / 2)     // 256 packed k-pairs
#define HCT    64             // h-tile held in smem at once
#define HCB    128            // h per prod block (2 tiles, looped)
#define NCHUNK (HDIM / HCB)   // 16 partial-product chunks
#define NSPLIT 4              // n-split for z-GEMM
#define NCK    (NDIM / NSPLIT)

// ---------------------------------------------------------------------------
// Device scratch (allocation-free rule: __device__ globals)
// ---------------------------------------------------------------------------
__device__ float              g_Tt[HDIM * BDIM];                  // [h][b] = tanh(z[b][h])
__device__ unsigned long long g_zp[NSPLIT * HDIM * (BDIM / 2)];   // z partials [ns][h][bp] packed
__device__ unsigned long long g_Ppart[NCHUNK * BDIM * KP];        // [c][b][kp] partial ratio-products

// ---------------------------------------------------------------------------
// f32x2 packed helpers
// ---------------------------------------------------------------------------
__device__ __forceinline__ unsigned long long pk2(float lo, float hi) {
    unsigned long long r;
    asm("mov.b64 %0, {%1, %2};" : "=l"(r) : "f"(lo), "f"(hi));
    return r;
}
__device__ __forceinline__ unsigned long long fma2(unsigned long long a, unsigned long long b, unsigned long long c) {
    unsigned long long r;
    asm("fma.rn.f32x2 %0, %1, %2, %3;" : "=l"(r) : "l"(a), "l"(b), "l"(c));
    return r;
}
__device__ __forceinline__ unsigned long long mul2(unsigned long long a, unsigned long long b) {
    unsigned long long r;
    asm("mul.rn.f32x2 %0, %1, %2;" : "=l"(r) : "l"(a), "l"(b));
    return r;
}
__device__ __forceinline__ unsigned long long add2(unsigned long long a, unsigned long long b) {
    unsigned long long r;
    asm("add.rn.f32x2 %0, %1, %2;" : "=l"(r) : "l"(a), "l"(b));
    return r;
}
__device__ __forceinline__ float2 up2(unsigned long long p) {
    float lo, hi;
    asm("mov.b64 {%0, %1}, %2;" : "=f"(lo), "=f"(hi) : "l"(p));
    return make_float2(lo, hi);
}

// ---------------------------------------------------------------------------
// Kernel 1: z partials. Thread = (1 h, 16 b as 8 packed accs), n-chunk NCK=128.
// grid (HDIM/256, BDIM/16, NSPLIT) = (8, 4, 4) = 128 blocks, block 256.
// ---------------------------------------------------------------------------
__global__ void __launch_bounds__(256) z_part_kernel(const float* __restrict__ W,
                                                     const float* __restrict__ x) {
    __shared__ float sx[NCK][16];  // [n_local][b_local]
    int t  = threadIdx.x;
    int h  = blockIdx.x * 256 + t;
    int b0 = blockIdx.y * 16;
    int n0 = blockIdx.z * NCK;

#pragma unroll
    for (int j = 0; j < 8; j++) {
        int idx = t + j * 256;               // 0..2047
        int bl = idx >> 7, nl = idx & 127;
        sx[nl][bl] = __ldg(x + (size_t)(b0 + bl) * NDIM + n0 + nl);
    }
    __syncthreads();

    unsigned long long acc[8];
#pragma unroll
    for (int i = 0; i < 8; i++) acc[i] = 0;  // packed +0.0

    const float* wp = W + (size_t)n0 * HDIM + h;
#pragma unroll 4
    for (int n = 0; n < NCK; n++) {
        float w = __ldg(wp + n * HDIM);      // coalesced across threads
        unsigned long long wd = pk2(w, w);
        const ulonglong2* xr = reinterpret_cast<const ulonglong2*>(&sx[n][0]);
        ulonglong2 xA = xr[0];               // b0+0..3  (broadcast)
        ulonglong2 xB = xr[1];               // b0+4..7
        ulonglong2 xC = xr[2];               // b0+8..11
        ulonglong2 xD = xr[3];               // b0+12..15
        acc[0] = fma2(xA.x, wd, acc[0]);
        acc[1] = fma2(xA.y, wd, acc[1]);
        acc[2] = fma2(xB.x, wd, acc[2]);
        acc[3] = fma2(xB.y, wd, acc[3]);
        acc[4] = fma2(xC.x, wd, acc[4]);
        acc[5] = fma2(xC.y, wd, acc[5]);
        acc[6] = fma2(xD.x, wd, acc[6]);
        acc[7] = fma2(xD.y, wd, acc[7]);
    }
    int bp0 = blockIdx.y * 8;
    ulonglong2* zp = reinterpret_cast<ulonglong2*>(
        g_zp + ((size_t)blockIdx.z * HDIM + h) * (BDIM / 2) + bp0);
#pragma unroll
    for (int i = 0; i < 4; i++)
        zp[i] = make_ulonglong2(acc[2 * i], acc[2 * i + 1]);
}

// ---------------------------------------------------------------------------
// Kernel 2: combine z partials + bias, tanh, write Tt[h][b].
// grid 256, block 256 (thread = (h, bp)); 4 independent loads.
// ---------------------------------------------------------------------------
__global__ void __launch_bounds__(256) z_comb_kernel(const float* __restrict__ bias) {
    int idx = blockIdx.x * 256 + threadIdx.x;   // 0..65535
    int h = idx >> 5, bp = idx & 31;
    const unsigned long long* zp = g_zp + (size_t)h * (BDIM / 2) + bp;
    unsigned long long v[NSPLIT];
#pragma unroll
    for (int ns = 0; ns < NSPLIT; ns++)
        v[ns] = __ldg(zp + (size_t)ns * (HDIM * BDIM / 2));
    unsigned long long s = add2(add2(v[0], v[1]), add2(v[2], v[3]));
    float2 z = up2(s);
    float bv = bias[h];
    float2 tv = make_float2(tanhf(z.x + bv), tanhf(z.y + bv));
    *reinterpret_cast<float2*>(g_Tt + (size_t)h * BDIM + 2 * bp) = tv;
}

// ---------------------------------------------------------------------------
// Kernel 3: main product kernel with fused C/S generation, 128 h per block.
//   Ppart[c][b][k] = prod_{h in chunk} ( cosh(2W[k,h]) - x[b,k]*tanh(z[b,h])*sinh(2W[k,h]) )
// Thread tile: 1 kp (2 k) x 4 b; warp = 32 kp x 4 b; block = 32 kp x 32 b.
// Block loops 2 smem tile passes of 64 h each.
// grid (KP/32, BDIM/32, NCHUNK) = (8, 2, 16) = 256 blocks, block 256.
// ---------------------------------------------------------------------------
__global__ void __launch_bounds__(256, 2) prod_kernel(const float* __restrict__ W,
                                                      const float* __restrict__ x) {
    __shared__ float sC[HCT][66];   // pad 66: conflict-free, LDS.64-aligned
    __shared__ float sS[HCT][66];
    int t    = threadIdx.x;
    int lane = t & 31;
    int w    = t >> 5;
    int k0   = blockIdx.x * 64;          // 64 k = 32 kp per block
    int b0   = blockIdx.y * 32 + w * 4;  // 4 b per thread
    int hb   = blockIdx.z * HCB;         // 128 h per block

    // -x signs for 4 b at this thread's kp (LDG.64, XOR sign flip)
    unsigned long long nx[4];
#pragma unroll
    for (int i = 0; i < 4; i++) {
        unsigned long long xv = *reinterpret_cast<const unsigned long long*>(
            x + (size_t)(b0 + i) * NDIM + k0 + 2 * lane);
        nx[i] = xv ^ 0x8000000080000000ULL;
    }

    unsigned long long acc[4];
#pragma unroll
    for (int i = 0; i < 4; i++) acc[i] = pk2(1.0f, 1.0f);

#pragma unroll
    for (int sub = 0; sub < HCB / HCT; sub++) {
        int h0 = hb + sub * HCT;
        if (sub) __syncthreads();   // previous tile fully consumed

        // Build C/S tile: coalesced W reads (lanes cover consecutive h), MUFU expf
#pragma unroll
        for (int j = 0; j < 16; j++) {
            int idx = t + j * 256;            // 0..4095 over 64k x 64h
            int hl = idx & 63, kl = idx >> 6;
            float wv = __ldg(W + (size_t)(k0 + kl) * HDIM + h0 + hl);
            float e  = __expf(2.0f * wv);
            float ei = __expf(-2.0f * wv);
            sC[hl][kl] = 0.5f * (e + ei);
            sS[hl][kl] = 0.5f * (e - ei);
        }
        __syncthreads();

        const float4* tp = reinterpret_cast<const float4*>(g_Tt + (size_t)h0 * BDIM + b0);
#pragma unroll 4
        for (int h = 0; h < HCT; h++) {
            unsigned long long Cp = *reinterpret_cast<const unsigned long long*>(&sC[h][2 * lane]);
            unsigned long long Sp = *reinterpret_cast<const unsigned long long*>(&sS[h][2 * lane]);
            float4 tv = __ldg(tp + h * (BDIM / 4));   // tanh b0..b0+3 (warp-uniform)
            acc[0] = mul2(acc[0], fma2(mul2(nx[0], pk2(tv.x, tv.x)), Sp, Cp));
            acc[1] = mul2(acc[1], fma2(mul2(nx[1], pk2(tv.y, tv.y)), Sp, Cp));
            acc[2] = mul2(acc[2], fma2(mul2(nx[2], pk2(tv.z, tv.z)), Sp, Cp));
            acc[3] = mul2(acc[3], fma2(mul2(nx[3], pk2(tv.w, tv.w)), Sp, Cp));
        }
    }

    int kp = blockIdx.x * 32 + lane;
    unsigned long long* out = g_Ppart + (size_t)blockIdx.z * (BDIM * KP);
#pragma unroll
    for (int i = 0; i < 4; i++)
        out[(size_t)(b0 + i) * KP + kp] = acc[i];
}

// ---------------------------------------------------------------------------
// Kernel 4: fused reduce, chunk-product parallelized across threads.
// grid BDIM, block 1024: thread = (kp, cg), cg in 0..3, each multiplies 4
// independent chunk values; partials combined via smem; first 256 threads
// apply ea = Oxy*exp(-2*x*a) and tree-sum over k.
// ---------------------------------------------------------------------------
__global__ void __launch_bounds__(1024) reduce_kernel(const float* __restrict__ x,
                                                      const float* __restrict__ a,
                                                      const float* __restrict__ Oxy,
                                                      float* __restrict__ out) {
    __shared__ unsigned long long sp[1024];
    __shared__ float ssum[8];
    int b  = blockIdx.x;
    int t  = threadIdx.x;
    int kp = t & 255;
    int cg = t >> 8;            // 0..3 -> chunks cg*4 .. cg*4+3

    const unsigned long long* P =
        g_Ppart + (size_t)(cg * 4) * (BDIM * KP) + (size_t)b * KP + kp;
    unsigned long long v[4];
#pragma unroll
    for (int i = 0; i < 4; i++)
        v[i] = __ldg(P + (size_t)i * (BDIM * KP));
    sp[t] = mul2(mul2(v[0], v[1]), mul2(v[2], v[3]));
    __syncthreads();

    if (t < 256) {
        unsigned long long p = mul2(mul2(sp[t], sp[t + 256]),
                                    mul2(sp[t + 512], sp[t + 768]));
        float2 pf = up2(p);
        float2 xv = *reinterpret_cast<const float2*>(x + (size_t)b * NDIM + 2 * kp);
        float2 av = *reinterpret_cast<const float2*>(a + 2 * kp);
        float2 ov = *reinterpret_cast<const float2*>(Oxy + 2 * kp);
        float e0 = ov.x * __expf(-2.0f * xv.x * av.x);
        float e1 = ov.y * __expf(-2.0f * xv.y * av.y);
        float s = pf.x * e0 + pf.y * e1;

#pragma unroll
        for (int o = 16; o; o >>= 1) s += __shfl_xor_sync(0xffffffffu, s, o);
        if ((t & 31) == 0) ssum[t >> 5] = s;
    }
    __syncthreads();
    if (t < 8) {
        float s2 = ssum[t];
#pragma unroll
        for (int o = 4; o; o >>= 1) s2 += __shfl_xor_sync(0x000000ffu, s2, o);
        if (t == 0) out[b] = s2;
    }
}

// ---------------------------------------------------------------------------
// Launch: 4 kernels
// ---------------------------------------------------------------------------
extern "C" void kernel_launch(void* const* d_in, const int* in_sizes, int n_in,
                              void* d_out, int out_size) {
    const float* x    = (const float*)d_in[0];   // [64,512]
    const float* W    = (const float*)d_in[1];   // [512,2048]
    const float* bias = (const float*)d_in[2];   // [2048]
    const float* a    = (const float*)d_in[3];   // [512]
    const float* Oxy  = (const float*)d_in[4];   // [512]
    float* out = (float*)d_out;                  // [64]

    z_part_kernel<<<dim3(HDIM / 256, BDIM / 16, NSPLIT), 256>>>(W, x);
    z_comb_kernel<<<256, 256>>>(bias);
    prod_kernel<<<dim3(KP / 32, BDIM / 32, NCHUNK), 256>>>(W, x);
    reduce_kernel<<<BDIM, 1024>>>(x, a, Oxy, out);
}